// round 6
// baseline (speedup 1.0000x reference)
#include <cuda_runtime.h>
#include <cuda_fp16.h>
#include <math.h>

#define BB 16
#define CC 64
#define HH 144
#define WW 144
#define hs 48
#define wsz 48
#define G9 9
#define C9 576
#define HW (hs*wsz)          // 2304
#define NPIX 36864.0f        // B*h*w
#define EPSV 1e-5f

typedef unsigned long long ull;

// ---- packed f32x2 helpers (sm_103a FFMA2 path) ----
__device__ __forceinline__ ull ffma2(ull a, ull b, ull c) {
    ull d; asm("fma.rn.f32x2 %0, %1, %2, %3;" : "=l"(d) : "l"(a), "l"(b), "l"(c)); return d;
}
__device__ __forceinline__ ull add2(ull a, ull b) {
    ull d; asm("add.rn.f32x2 %0, %1, %2;" : "=l"(d) : "l"(a), "l"(b)); return d;
}
__device__ __forceinline__ ull pack2(float lo, float hi) {
    ull d; asm("mov.b64 %0, {%1, %2};" : "=l"(d) : "f"(lo), "f"(hi)); return d;
}
__device__ __forceinline__ void unpack2(ull v, float& lo, float& hi) {
    asm("mov.b64 {%0, %1}, %2;" : "=f"(lo), "=f"(hi) : "l"(v));
}

// ---- static scratch (fp16 for the two big intermediates) ----
__device__ __half g_focus[BB*C9*HW];   // 42.5 MB
__device__ __half g_mixed[BB*C9*HW];   // 42.5 MB
__device__ float  g_s[BB*CC*HW];       // 9.4 MB
__device__ float  g_sum1[C9], g_sq1[C9];
__device__ float  g_sum2[CC], g_sq2[CC];

// ---------------------------------------------------------------
// K1: maxpool3x3 + focus_downsample fused; zero bn accumulators.
// ---------------------------------------------------------------
__global__ void k_pool_focus(const float* __restrict__ x) {
    if (blockIdx.x == 0) {
        for (int i = threadIdx.x; i < C9; i += 256) { g_sum1[i] = 0.f; g_sq1[i] = 0.f; }
        if (threadIdx.x < CC) { g_sum2[threadIdx.x] = 0.f; g_sq2[threadIdx.x] = 0.f; }
    }
    int idx = blockIdx.x * 256 + threadIdx.x;
    if (idx >= BB*CC*HW) return;
    int ww = idx % wsz; int t = idx / wsz;
    int hh = t % hs;    t /= hs;
    int c  = t % CC;    int b = t / CC;

    const float* xp = x + (size_t)(b*CC + c) * HH * WW;
    int r0 = hh*3 - 1, c0 = ww*3 - 1;
    float v[5][5];
#pragma unroll
    for (int r = 0; r < 5; r++) {
        int rr = r0 + r; bool rok = (rr >= 0 && rr < HH);
#pragma unroll
        for (int q = 0; q < 5; q++) {
            int cc = c0 + q;
            v[r][q] = (rok && cc >= 0 && cc < WW) ? xp[rr*WW + cc] : -INFINITY;
        }
    }
    float hm[5][3];
#pragma unroll
    for (int r = 0; r < 5; r++)
#pragma unroll
        for (int j = 0; j < 3; j++)
            hm[r][j] = fmaxf(fmaxf(v[r][j], v[r][j+1]), v[r][j+2]);
#pragma unroll
    for (int i = 0; i < 3; i++)
#pragma unroll
        for (int j = 0; j < 3; j++) {
            float m = fmaxf(fmaxf(hm[i][j], hm[i+1][j]), hm[i+2][j]);
            g_focus[((size_t)b*C9 + (i*3+j)*CC + c) * HW + hh*wsz + ww] = __float2half(m);
        }
}

// ---------------------------------------------------------------
// K2: mixer GEMM with packed f32x2 FMA.
// Weights pre-packed as broadcast pairs in smem (uniform LDS.64).
// fp16 in (g_focus) / fp16 out (g_mixed); all math fp32.
// ---------------------------------------------------------------
__global__ void k_mixer(const float* __restrict__ wmix) {
    __shared__ __align__(16) ull   Wp[64*64];   // 32 KB, (w,w) pairs
    __shared__ __align__(16) float Xs[16*256];  // 16 KB
    int tid = threadIdx.x;
    int pt = blockIdx.x, g = blockIdx.y, b = blockIdx.z;

    const float* wg = wmix + g*4096;
#pragma unroll
    for (int k = 0; k < 16; k++) {
        float w = wg[tid + k*256];
        Wp[tid + k*256] = pack2(w, w);
    }

    size_t base = ((size_t)b*C9 + g*CC) * HW + pt*256;
    int tp = tid & 31, to = tid >> 5;

    ull acc2[8][4];
#pragma unroll
    for (int oo = 0; oo < 8; oo++)
#pragma unroll
        for (int j = 0; j < 4; j++) acc2[oo][j] = 0ull;

    for (int kc = 0; kc < 4; kc++) {
        __syncthreads();
#pragma unroll
        for (int k = 0; k < 16; k++) {
            int e = tid + k*256; int i = e >> 8; int p = e & 255;
            Xs[e] = __half2float(g_focus[base + (size_t)(kc*16 + i)*HW + p]);
        }
        __syncthreads();
#pragma unroll
        for (int i = 0; i < 16; i++) {
            int ig = kc*16 + i;
            ull b2[4];
            const ull* xr = (const ull*)&Xs[i*256 + tp*8];
            b2[0] = xr[0]; b2[1] = xr[1]; b2[2] = xr[2]; b2[3] = xr[3];
#pragma unroll
            for (int oo = 0; oo < 8; oo++) {
                ull a2 = Wp[(to*8+oo)*64 + ig];
#pragma unroll
                for (int j = 0; j < 4; j++)
                    acc2[oo][j] = ffma2(a2, b2[j], acc2[oo][j]);
            }
        }
    }
    __half* outp = g_mixed + base;
#pragma unroll
    for (int oo = 0; oo < 8; oo++) {
        int o = to*8 + oo;
        float v[8];
#pragma unroll
        for (int j = 0; j < 4; j++) unpack2(acc2[oo][j], v[2*j], v[2*j+1]);
        __half2 hv[4];
#pragma unroll
        for (int j = 0; j < 4; j++) hv[j] = __floats2half2_rn(v[2*j], v[2*j+1]);
        *(uint4*)&outp[(size_t)o*HW + tp*8] = *(const uint4*)hv;
        // bn1 partials (fp32 accumulators)
        ull S = add2(add2(acc2[oo][0], acc2[oo][1]), add2(acc2[oo][2], acc2[oo][3]));
        ull Q = 0ull;
#pragma unroll
        for (int j = 0; j < 4; j++) Q = ffma2(acc2[oo][j], acc2[oo][j], Q);
        float sl, sh2, ql, qh; unpack2(S, sl, sh2); unpack2(Q, ql, qh);
        float s = sl + sh2, q = ql + qh;
#pragma unroll
        for (int off = 16; off > 0; off >>= 1) {
            s += __shfl_xor_sync(0xffffffffu, s, off);
            q += __shfl_xor_sync(0xffffffffu, q, off);
        }
        if (tp == 0) {
            int ch = g*CC + to*8 + oo;
            atomicAdd(&g_sum1[ch], s);
            atomicAdd(&g_sq1[ch], q);
        }
    }
}

// ---------------------------------------------------------------
// K3: fused 4-way dwconv, TWO channels per block packed as f32x2.
// ---------------------------------------------------------------
#define TSTR 68
__global__ __launch_bounds__(256, 2)
void k_conv(const float* __restrict__ wh1, const float* __restrict__ wv1,
            const float* __restrict__ wh2, const float* __restrict__ wv2,
            const float* __restrict__ gm,  const float* __restrict__ bm) {
    __shared__ float2 T2[60*TSTR];
    __shared__ float2 sw1[33], sv1[33], sw2[33], sv2[33];
    __shared__ float rs0[8], rq0[8], rs1[8], rq1[8];
    int tid = threadIdx.x;
    int bc = blockIdx.x; int cp = bc & 31; int b = bc >> 5;
    int c0 = cp*2, c1 = c0 + 1;

    float mn0 = g_sum1[c0] / NPIX, mn1 = g_sum1[c1] / NPIX;
    float vr0 = g_sq1[c0] / NPIX - mn0*mn0, vr1 = g_sq1[c1] / NPIX - mn1*mn1;
    float sc0 = gm[c0] * rsqrtf(vr0 + EPSV), sc1 = gm[c1] * rsqrtf(vr1 + EPSV);
    float sh0 = bm[c0] - mn0*sc0,            sh1 = bm[c1] - mn1*sc1;

    const __half* p0 = g_mixed + ((size_t)b*C9 + c0) * HW;
    const __half* p1 = p0 + HW;
    for (int e = tid; e < 60*TSTR; e += 256) {
        int tr = e / TSTR, tc = e % TSTR;
        int r = tr - 6, q = tc - 9;
        float2 v = make_float2(0.f, 0.f);
        if (r >= 0 && r < hs && q >= 0 && q < wsz) {
            v.x = fmaf(__half2float(p0[r*wsz + q]), sc0, sh0);
            v.y = fmaf(__half2float(p1[r*wsz + q]), sc1, sh1);
        }
        T2[e] = v;
    }
    if (tid < 132) {
        int a = tid / 33, j = tid % 33;
        const float* src = (a == 0) ? wh1 : (a == 1) ? wv1 : (a == 2) ? wh2 : wv2;
        float2 w = make_float2(src[c0*33 + j], src[c1*33 + j]);
        if (a == 0) sw1[j] = w; else if (a == 1) sv1[j] = w;
        else if (a == 2) sw2[j] = w; else sv2[j] = w;
    }
    __syncthreads();

    int tx = tid & 15, ty = tid >> 4;
    int i0 = ty*3, j0 = tx*3;
    ull acc[3][3];
#pragma unroll
    for (int a = 0; a < 3; a++)
#pragma unroll
        for (int bq = 0; bq < 3; bq++) acc[a][bq] = 0ull;

#define T2AT(r,q) (*(const ull*)&T2[((r)+6)*TSTR + ((q)+9)])

    // ---- h1: vertical 11-tap, 3 weight columns ----
#pragma unroll
    for (int v = 0; v < 3; v++) {
        ull wr[11];
#pragma unroll
        for (int u = 0; u < 11; u++) wr[u] = *(const ull*)&sw1[u*3 + v];
        int dc = v - 1;
#pragma unroll
        for (int ox = 0; ox < 3; ox++) {
            ull col[13];
#pragma unroll
            for (int t = 0; t < 13; t++) col[t] = T2AT(i0 + t - 5, j0 + ox + dc);
#pragma unroll
            for (int oy = 0; oy < 3; oy++)
#pragma unroll
                for (int u = 0; u < 11; u++)
                    acc[oy][ox] = ffma2(wr[u], col[oy + u], acc[oy][ox]);
        }
    }
    // ---- v1: horizontal 11-tap, 3 weight rows ----
#pragma unroll
    for (int u = 0; u < 3; u++) {
        ull wr[11];
#pragma unroll
        for (int v = 0; v < 11; v++) wr[v] = *(const ull*)&sv1[u*11 + v];
        int dr = u - 1;
#pragma unroll
        for (int oy = 0; oy < 3; oy++) {
            ull row[13];
#pragma unroll
            for (int t = 0; t < 13; t++) row[t] = T2AT(i0 + oy + dr, j0 + t - 5);
#pragma unroll
            for (int ox = 0; ox < 3; ox++)
#pragma unroll
                for (int v = 0; v < 11; v++)
                    acc[oy][ox] = ffma2(wr[v], row[ox + v], acc[oy][ox]);
        }
    }
    // ---- h2 + w2: shared anti-diagonal strips ----
#pragma unroll
    for (int ee = 0; ee < 3; ee++) {
        int e = ee - 1;
        ull wA[11], wB[11];
#pragma unroll
        for (int u = 0; u < 11; u++) wA[u] = *(const ull*)&sw2[u*3 + ee];
#pragma unroll
        for (int v = 0; v < 11; v++) wB[v] = *(const ull*)&sv2[ee*11 + v];
#pragma unroll
        for (int s2 = 0; s2 < 5; s2++) {
            int d = s2 + e;
            ull strip[15];
#pragma unroll
            for (int s = 0; s < 15; s++)
                strip[s] = T2AT(i0 + s - 6, j0 + d + 6 - s);
#pragma unroll
            for (int oy = 0; oy < 3; oy++) {
                int ox = s2 - oy;
                if (ox < 0 || ox > 2) continue;
#pragma unroll
                for (int u = 0; u < 11; u++)
                    acc[oy][ox] = ffma2(wA[u], strip[oy + u + 1], acc[oy][ox]);
#pragma unroll
                for (int v = 0; v < 11; v++)
                    acc[oy][ox] = ffma2(wB[v], strip[oy + e - v + 11], acc[oy][ox]);
            }
        }
    }
#undef T2AT

    // store + bn2 partials
    float* sp0 = g_s + ((size_t)b*CC + c0) * HW;
    float* sp1 = sp0 + HW;
    ull S = 0ull, Q = 0ull;
#pragma unroll
    for (int oy = 0; oy < 3; oy++)
#pragma unroll
        for (int ox = 0; ox < 3; ox++) {
            float v0, v1; unpack2(acc[oy][ox], v0, v1);
            sp0[(i0 + oy)*wsz + j0 + ox] = v0;
            sp1[(i0 + oy)*wsz + j0 + ox] = v1;
            S = add2(S, acc[oy][ox]);
            Q = ffma2(acc[oy][ox], acc[oy][ox], Q);
        }
    float s0, s1, q0, q1; unpack2(S, s0, s1); unpack2(Q, q0, q1);
#pragma unroll
    for (int off = 16; off > 0; off >>= 1) {
        s0 += __shfl_xor_sync(0xffffffffu, s0, off);
        q0 += __shfl_xor_sync(0xffffffffu, q0, off);
        s1 += __shfl_xor_sync(0xffffffffu, s1, off);
        q1 += __shfl_xor_sync(0xffffffffu, q1, off);
    }
    int lane = tid & 31, wid = tid >> 5;
    if (lane == 0) { rs0[wid] = s0; rq0[wid] = q0; rs1[wid] = s1; rq1[wid] = q1; }
    __syncthreads();
    if (tid == 0) {
        float a0 = 0.f, b0v = 0.f, a1 = 0.f, b1v = 0.f;
#pragma unroll
        for (int w = 0; w < 8; w++) { a0 += rs0[w]; b0v += rq0[w]; a1 += rs1[w]; b1v += rq1[w]; }
        atomicAdd(&g_sum2[c0], a0); atomicAdd(&g_sq2[c0], b0v);
        atomicAdd(&g_sum2[c1], a1); atomicAdd(&g_sq2[c1], b1v);
    }
}

// ---------------------------------------------------------------
// K4: concat + pixel_shuffle3 + sigmoid gate; BN finalize inline.
// Phase 1: coalesced att gather (hh,ww mapping) + sigmoid -> smem
// Phase 2: fully coalesced x load / gate / out store.
// ---------------------------------------------------------------
__global__ void k_final(const float* __restrict__ x, float* __restrict__ out,
                        const float* __restrict__ gm, const float* __restrict__ bm,
                        const float* __restrict__ gn, const float* __restrict__ bn) {
    __shared__ float ssc[9], ssh[9];
    __shared__ float sm[12*144];                 // sigmoid(att) tile, 6.9 KB
    int c = blockIdx.y, b = blockIdx.z;
    int tid = threadIdx.y * 48 + threadIdx.x;    // 0..191
    if (tid < 9) {
        int k = c*9 + tid;
        float mean, var, sc, sh;
        if (k < CC) {
            mean = g_sum2[k] / NPIX; var = g_sq2[k] / NPIX - mean*mean;
            sc = gn[k] * rsqrtf(var + EPSV); sh = bn[k] - mean*sc;
        } else {
            mean = g_sum1[k] / NPIX; var = g_sq1[k] / NPIX - mean*mean;
            sc = gm[k] * rsqrtf(var + EPSV); sh = bm[k] - mean*sc;
        }
        ssc[tid] = sc; ssh[tid] = sh;
    }
    __syncthreads();

    int ww = threadIdx.x;                        // 0..47
    int ty = threadIdx.y;                        // 0..3
    int hh = blockIdx.x * 4 + ty;                // source row
    size_t pix = (size_t)hh*wsz + ww;

#pragma unroll
    for (int t = 0; t < 9; t++) {
        int k = c*9 + t;
        float v = (k < CC) ? g_s[((size_t)b*CC + k)*HW + pix]
                           : __half2float(g_mixed[((size_t)b*C9 + k)*HW + pix]);
        float a = fmaf(v, ssc[t], ssh[t]);
        float sig = 1.f / (1.f + __expf(-a));
        int r = t / 3, s2 = t - r*3;
        sm[(ty*3 + r)*144 + ww*3 + s2] = sig;
    }
    __syncthreads();

    int y0 = blockIdx.x * 12;                    // output row base
    const float* xp = x  + ((size_t)(b*CC + c) * HH + y0) * WW;
    float*       op = out + ((size_t)(b*CC + c) * HH + y0) * WW;
#pragma unroll
    for (int it = 0; it < 9; it++) {
        int e = it*192 + tid;                    // 0..1727 contiguous
        op[e] = xp[e] * sm[e];
    }
}

// ---------------------------------------------------------------
extern "C" void kernel_launch(void* const* d_in, const int* in_sizes, int n_in,
                              void* d_out, int out_size) {
    const float* x       = (const float*)d_in[0];
    const float* w_mixer = (const float*)d_in[1];
    const float* g_mnorm = (const float*)d_in[2];
    const float* b_mnorm = (const float*)d_in[3];
    const float* w_h1    = (const float*)d_in[4];
    const float* w_v1    = (const float*)d_in[5];
    const float* w_h2    = (const float*)d_in[6];
    const float* w_v2    = (const float*)d_in[7];
    const float* g_norm  = (const float*)d_in[8];
    const float* b_norm  = (const float*)d_in[9];

    k_pool_focus<<<(BB*CC*HW + 255)/256, 256>>>(x);
    k_mixer<<<dim3(9, 9, 16), 256>>>(w_mixer);
    k_conv<<<BB*32, 256>>>(w_h1, w_v1, w_h2, w_v2, g_mnorm, b_mnorm);
    k_final<<<dim3(12, 64, 16), dim3(48, 4)>>>(x, (float*)d_out, g_mnorm, b_mnorm, g_norm, b_norm);
}

// round 10
// speedup vs baseline: 1.0660x; 1.0660x over previous
#include <cuda_runtime.h>
#include <cuda_fp16.h>
#include <math.h>

#define BB 16
#define CC 64
#define HH 144
#define WW 144
#define hs 48
#define wsz 48
#define G9 9
#define C9 576
#define HW (hs*wsz)          // 2304
#define NPIX 36864.0f        // B*h*w
#define EPSV 1e-5f

typedef unsigned long long ull;

// ---- packed f32x2 helpers (sm_103a FFMA2 path) ----
__device__ __forceinline__ ull ffma2(ull a, ull b, ull c) {
    ull d; asm("fma.rn.f32x2 %0, %1, %2, %3;" : "=l"(d) : "l"(a), "l"(b), "l"(c)); return d;
}
__device__ __forceinline__ ull add2(ull a, ull b) {
    ull d; asm("add.rn.f32x2 %0, %1, %2;" : "=l"(d) : "l"(a), "l"(b)); return d;
}
__device__ __forceinline__ ull pack2(float lo, float hi) {
    ull d; asm("mov.b64 %0, {%1, %2};" : "=l"(d) : "f"(lo), "f"(hi)); return d;
}
__device__ __forceinline__ void unpack2(ull v, float& lo, float& hi) {
    asm("mov.b64 {%0, %1}, %2;" : "=f"(lo), "=f"(hi) : "l"(v));
}

// ---- static scratch ----
__device__ __align__(16) __half g_focus[BB*C9*HW];   // 42.5 MB
__device__ __align__(16) __half g_mixed[BB*C9*HW];   // 42.5 MB
__device__ __align__(16) float  g_s[BB*CC*HW];       // 9.4 MB
__device__ float  g_sum1[C9], g_sq1[C9];
__device__ float  g_sum2[CC], g_sq2[CC];

// ---------------------------------------------------------------
// K1: maxpool3x3 + focus, smem-tiled separable max.
// Block = (tile of 12 focus rows, c, b). x tile 38x144 loaded once.
// ---------------------------------------------------------------
__global__ __launch_bounds__(256)
void k_pool_focus(const float* __restrict__ x) {
    __shared__ float xt[38*144];
    __shared__ float hm[38*144];
    int tid = threadIdx.x;
    int tile = blockIdx.x, c = blockIdx.y, b = blockIdx.z;
    if (tile == 0 && c == 0 && b == 0) {
        for (int i = tid; i < C9; i += 256) { g_sum1[i] = 0.f; g_sq1[i] = 0.f; }
        if (tid < CC) { g_sum2[tid] = 0.f; g_sq2[tid] = 0.f; }
    }
    int y0 = tile*36 - 1;                      // abs x-row of xt row 0
    const float* xp = x + (size_t)(b*CC + c) * HH * WW;
    // load 38 rows x 144 cols as float4 (rows OOB -> -inf)
    for (int e = tid; e < 38*36; e += 256) {
        int rr = e / 36, c4 = e % 36;
        int y = y0 + rr;
        float4 v;
        if (y >= 0 && y < HH) v = *(const float4*)&xp[(size_t)y*WW + c4*4];
        else v = make_float4(-INFINITY, -INFINITY, -INFINITY, -INFINITY);
        *(float4*)&xt[rr*144 + c4*4] = v;
    }
    __syncthreads();
    // horizontal 3-max
    for (int e = tid; e < 38*144; e += 256) {
        int xc = e % 144;
        float m = xt[e];
        if (xc > 0)   m = fmaxf(m, xt[e-1]);
        if (xc < 143) m = fmaxf(m, xt[e+1]);
        hm[e] = m;
    }
    __syncthreads();
    // vertical 3-max -> 9 focus outputs per source pixel
    for (int e = tid; e < 576; e += 256) {
        int hl = e / 48, ww = e % 48;
        int base = (3*hl)*144 + 3*ww;
        float h[5][3];
#pragma unroll
        for (int dy = 0; dy < 5; dy++)
#pragma unroll
            for (int j = 0; j < 3; j++) h[dy][j] = hm[base + dy*144 + j];
        int hh = tile*12 + hl;
        size_t pbase = (size_t)b*C9*HW + (size_t)hh*wsz + ww;
#pragma unroll
        for (int i = 0; i < 3; i++)
#pragma unroll
            for (int j = 0; j < 3; j++) {
                float m = fmaxf(fmaxf(h[i][j], h[i+1][j]), h[i+2][j]);
                g_focus[pbase + (size_t)((i*3+j)*CC + c)*HW] = __float2half(m);
            }
    }
}

// ---------------------------------------------------------------
// K2: mixer GEMM with packed f32x2 FMA. fp16 I/O, fp32 math.
// ---------------------------------------------------------------
__global__ void k_mixer(const float* __restrict__ wmix) {
    __shared__ __align__(16) ull   Wp[64*64];
    __shared__ __align__(16) float Xs[16*256];
    int tid = threadIdx.x;
    int pt = blockIdx.x, g = blockIdx.y, b = blockIdx.z;

    const float* wg = wmix + g*4096;
#pragma unroll
    for (int k = 0; k < 16; k++) {
        float w = wg[tid + k*256];
        Wp[tid + k*256] = pack2(w, w);
    }

    size_t base = ((size_t)b*C9 + g*CC) * HW + pt*256;
    int tp = tid & 31, to = tid >> 5;

    ull acc2[8][4];
#pragma unroll
    for (int oo = 0; oo < 8; oo++)
#pragma unroll
        for (int j = 0; j < 4; j++) acc2[oo][j] = 0ull;

    for (int kc = 0; kc < 4; kc++) {
        __syncthreads();
#pragma unroll
        for (int k = 0; k < 16; k++) {
            int e = tid + k*256; int i = e >> 8; int p = e & 255;
            Xs[e] = __half2float(g_focus[base + (size_t)(kc*16 + i)*HW + p]);
        }
        __syncthreads();
#pragma unroll
        for (int i = 0; i < 16; i++) {
            int ig = kc*16 + i;
            ull b2[4];
            const ull* xr = (const ull*)&Xs[i*256 + tp*8];
            b2[0] = xr[0]; b2[1] = xr[1]; b2[2] = xr[2]; b2[3] = xr[3];
#pragma unroll
            for (int oo = 0; oo < 8; oo++) {
                ull a2 = Wp[(to*8+oo)*64 + ig];
#pragma unroll
                for (int j = 0; j < 4; j++)
                    acc2[oo][j] = ffma2(a2, b2[j], acc2[oo][j]);
            }
        }
    }
    __half* outp = g_mixed + base;
#pragma unroll
    for (int oo = 0; oo < 8; oo++) {
        int o = to*8 + oo;
        float v[8];
#pragma unroll
        for (int j = 0; j < 4; j++) unpack2(acc2[oo][j], v[2*j], v[2*j+1]);
        __half2 hv[4];
#pragma unroll
        for (int j = 0; j < 4; j++) hv[j] = __floats2half2_rn(v[2*j], v[2*j+1]);
        *(uint4*)&outp[(size_t)o*HW + tp*8] = *(const uint4*)hv;
        ull S = add2(add2(acc2[oo][0], acc2[oo][1]), add2(acc2[oo][2], acc2[oo][3]));
        ull Q = 0ull;
#pragma unroll
        for (int j = 0; j < 4; j++) Q = ffma2(acc2[oo][j], acc2[oo][j], Q);
        float sl, sh2, ql, qh; unpack2(S, sl, sh2); unpack2(Q, ql, qh);
        float s = sl + sh2, q = ql + qh;
#pragma unroll
        for (int off = 16; off > 0; off >>= 1) {
            s += __shfl_xor_sync(0xffffffffu, s, off);
            q += __shfl_xor_sync(0xffffffffu, q, off);
        }
        if (tp == 0) {
            int ch = g*CC + to*8 + oo;
            atomicAdd(&g_sum1[ch], s);
            atomicAdd(&g_sq1[ch], q);
        }
    }
}

// ---------------------------------------------------------------
// K3: fused 4-way dwconv, two channels per block packed f32x2.
// ---------------------------------------------------------------
#define TSTR 68
__global__ __launch_bounds__(256, 2)
void k_conv(const float* __restrict__ wh1, const float* __restrict__ wv1,
            const float* __restrict__ wh2, const float* __restrict__ wv2,
            const float* __restrict__ gm,  const float* __restrict__ bm) {
    __shared__ float2 T2[60*TSTR];
    __shared__ float2 sw1[33], sv1[33], sw2[33], sv2[33];
    __shared__ float rs0[8], rq0[8], rs1[8], rq1[8];
    int tid = threadIdx.x;
    int bc = blockIdx.x; int cp = bc & 31; int b = bc >> 5;
    int c0 = cp*2, c1 = c0 + 1;

    float mn0 = g_sum1[c0] / NPIX, mn1 = g_sum1[c1] / NPIX;
    float vr0 = g_sq1[c0] / NPIX - mn0*mn0, vr1 = g_sq1[c1] / NPIX - mn1*mn1;
    float sc0 = gm[c0] * rsqrtf(vr0 + EPSV), sc1 = gm[c1] * rsqrtf(vr1 + EPSV);
    float sh0 = bm[c0] - mn0*sc0,            sh1 = bm[c1] - mn1*sc1;

    const __half* p0 = g_mixed + ((size_t)b*C9 + c0) * HW;
    const __half* p1 = p0 + HW;
    for (int e = tid; e < 60*TSTR; e += 256) {
        int tr = e / TSTR, tc = e % TSTR;
        int r = tr - 6, q = tc - 9;
        float2 v = make_float2(0.f, 0.f);
        if (r >= 0 && r < hs && q >= 0 && q < wsz) {
            v.x = fmaf(__half2float(p0[r*wsz + q]), sc0, sh0);
            v.y = fmaf(__half2float(p1[r*wsz + q]), sc1, sh1);
        }
        T2[e] = v;
    }
    if (tid < 132) {
        int a = tid / 33, j = tid % 33;
        const float* src = (a == 0) ? wh1 : (a == 1) ? wv1 : (a == 2) ? wh2 : wv2;
        float2 w = make_float2(src[c0*33 + j], src[c1*33 + j]);
        if (a == 0) sw1[j] = w; else if (a == 1) sv1[j] = w;
        else if (a == 2) sw2[j] = w; else sv2[j] = w;
    }
    __syncthreads();

    int tx = tid & 15, ty = tid >> 4;
    int i0 = ty*3, j0 = tx*3;
    ull acc[3][3];
#pragma unroll
    for (int a = 0; a < 3; a++)
#pragma unroll
        for (int bq = 0; bq < 3; bq++) acc[a][bq] = 0ull;

#define T2AT(r,q) (*(const ull*)&T2[((r)+6)*TSTR + ((q)+9)])

#pragma unroll
    for (int v = 0; v < 3; v++) {
        ull wr[11];
#pragma unroll
        for (int u = 0; u < 11; u++) wr[u] = *(const ull*)&sw1[u*3 + v];
        int dc = v - 1;
#pragma unroll
        for (int ox = 0; ox < 3; ox++) {
            ull col[13];
#pragma unroll
            for (int t = 0; t < 13; t++) col[t] = T2AT(i0 + t - 5, j0 + ox + dc);
#pragma unroll
            for (int oy = 0; oy < 3; oy++)
#pragma unroll
                for (int u = 0; u < 11; u++)
                    acc[oy][ox] = ffma2(wr[u], col[oy + u], acc[oy][ox]);
        }
    }
#pragma unroll
    for (int u = 0; u < 3; u++) {
        ull wr[11];
#pragma unroll
        for (int v = 0; v < 11; v++) wr[v] = *(const ull*)&sv1[u*11 + v];
        int dr = u - 1;
#pragma unroll
        for (int oy = 0; oy < 3; oy++) {
            ull row[13];
#pragma unroll
            for (int t = 0; t < 13; t++) row[t] = T2AT(i0 + oy + dr, j0 + t - 5);
#pragma unroll
            for (int ox = 0; ox < 3; ox++)
#pragma unroll
                for (int v = 0; v < 11; v++)
                    acc[oy][ox] = ffma2(wr[v], row[ox + v], acc[oy][ox]);
        }
    }
#pragma unroll
    for (int ee = 0; ee < 3; ee++) {
        int e = ee - 1;
        ull wA[11], wB[11];
#pragma unroll
        for (int u = 0; u < 11; u++) wA[u] = *(const ull*)&sw2[u*3 + ee];
#pragma unroll
        for (int v = 0; v < 11; v++) wB[v] = *(const ull*)&sv2[ee*11 + v];
#pragma unroll
        for (int s2 = 0; s2 < 5; s2++) {
            int d = s2 + e;
            ull strip[15];
#pragma unroll
            for (int s = 0; s < 15; s++)
                strip[s] = T2AT(i0 + s - 6, j0 + d + 6 - s);
#pragma unroll
            for (int oy = 0; oy < 3; oy++) {
                int ox = s2 - oy;
                if (ox < 0 || ox > 2) continue;
#pragma unroll
                for (int u = 0; u < 11; u++)
                    acc[oy][ox] = ffma2(wA[u], strip[oy + u + 1], acc[oy][ox]);
#pragma unroll
                for (int v = 0; v < 11; v++)
                    acc[oy][ox] = ffma2(wB[v], strip[oy + e - v + 11], acc[oy][ox]);
            }
        }
    }
#undef T2AT

    float* sp0 = g_s + ((size_t)b*CC + c0) * HW;
    float* sp1 = sp0 + HW;
    ull S = 0ull, Q = 0ull;
#pragma unroll
    for (int oy = 0; oy < 3; oy++)
#pragma unroll
        for (int ox = 0; ox < 3; ox++) {
            float v0, v1; unpack2(acc[oy][ox], v0, v1);
            sp0[(i0 + oy)*wsz + j0 + ox] = v0;
            sp1[(i0 + oy)*wsz + j0 + ox] = v1;
            S = add2(S, acc[oy][ox]);
            Q = ffma2(acc[oy][ox], acc[oy][ox], Q);
        }
    float s0, s1, q0, q1; unpack2(S, s0, s1); unpack2(Q, q0, q1);
#pragma unroll
    for (int off = 16; off > 0; off >>= 1) {
        s0 += __shfl_xor_sync(0xffffffffu, s0, off);
        q0 += __shfl_xor_sync(0xffffffffu, q0, off);
        s1 += __shfl_xor_sync(0xffffffffu, s1, off);
        q1 += __shfl_xor_sync(0xffffffffu, q1, off);
    }
    int lane = tid & 31, wid = tid >> 5;
    if (lane == 0) { rs0[wid] = s0; rq0[wid] = q0; rs1[wid] = s1; rq1[wid] = q1; }
    __syncthreads();
    if (tid == 0) {
        float a0 = 0.f, b0v = 0.f, a1 = 0.f, b1v = 0.f;
#pragma unroll
        for (int w = 0; w < 8; w++) { a0 += rs0[w]; b0v += rq0[w]; a1 += rs1[w]; b1v += rq1[w]; }
        atomicAdd(&g_sum2[c0], a0); atomicAdd(&g_sq2[c0], b0v);
        atomicAdd(&g_sum2[c1], a1); atomicAdd(&g_sq2[c1], b1v);
    }
}

// ---------------------------------------------------------------
// K4: concat + pixel_shuffle3 + sigmoid gate. Barrier-free 128-bit.
// Thread owns 12 consecutive output pixels of one row (12 = lcm(3,4)):
// 3 float4 att loads + 3 float4 x loads + 3 float4 stores.
// ---------------------------------------------------------------
__global__ __launch_bounds__(192)
void k_final(const float* __restrict__ x, float* __restrict__ out,
             const float* __restrict__ gm, const float* __restrict__ bm,
             const float* __restrict__ gn, const float* __restrict__ bn) {
    __shared__ float ssc[9], ssh[9];
    int c = blockIdx.y, b = blockIdx.z;
    int tid = threadIdx.x;                        // 0..191
    if (tid < 9) {
        int k = c*9 + tid;
        float mean, var, sc, sh;
        if (k < CC) {
            mean = g_sum2[k] / NPIX; var = g_sq2[k] / NPIX - mean*mean;
            sc = gn[k] * rsqrtf(var + EPSV); sh = bn[k] - mean*sc;
        } else {
            mean = g_sum1[k] / NPIX; var = g_sq1[k] / NPIX - mean*mean;
            sc = gm[k] * rsqrtf(var + EPSV); sh = bm[k] - mean*sc;
        }
        ssc[tid] = sc; ssh[tid] = sh;
    }
    __syncthreads();

    int row = blockIdx.x * 16 + tid / 12;         // output row 0..143
    int k   = tid % 12;                           // 12-px column group
    int r = row % 3, hh = row / 3, ww0 = k * 4;
    size_t spix = (size_t)hh*wsz + ww0;

    float sg[3][4];
#pragma unroll
    for (int s = 0; s < 3; s++) {
        int t = r*3 + s;
        int ch = c*9 + t;
        float4 v;
        if (ch < CC) {
            v = *(const float4*)&g_s[((size_t)b*CC + ch)*HW + spix];
        } else {
            uint2 u = *(const uint2*)&g_mixed[((size_t)b*C9 + ch)*HW + spix];
            __half2 h0 = *(__half2*)&u.x, h1 = *(__half2*)&u.y;
            v = make_float4(__low2float(h0), __high2float(h0),
                            __low2float(h1), __high2float(h1));
        }
        float sc = ssc[t], sh = ssh[t];
        sg[s][0] = 1.f / (1.f + __expf(-fmaf(v.x, sc, sh)));
        sg[s][1] = 1.f / (1.f + __expf(-fmaf(v.y, sc, sh)));
        sg[s][2] = 1.f / (1.f + __expf(-fmaf(v.z, sc, sh)));
        sg[s][3] = 1.f / (1.f + __expf(-fmaf(v.w, sc, sh)));
    }

    const float* xr = x   + ((size_t)(b*CC + c)*HH + row)*WW + k*12;
    float*       op = out + ((size_t)(b*CC + c)*HH + row)*WW + k*12;
    float4 x0 = *(const float4*)&xr[0];
    float4 x1 = *(const float4*)&xr[4];
    float4 x2 = *(const float4*)&xr[8];
    float4 o0 = make_float4(x0.x*sg[0][0], x0.y*sg[1][0], x0.z*sg[2][0], x0.w*sg[0][1]);
    float4 o1 = make_float4(x1.x*sg[1][1], x1.y*sg[2][1], x1.z*sg[0][2], x1.w*sg[1][2]);
    float4 o2 = make_float4(x2.x*sg[2][2], x2.y*sg[0][3], x2.z*sg[1][3], x2.w*sg[2][3]);
    *(float4*)&op[0] = o0;
    *(float4*)&op[4] = o1;
    *(float4*)&op[8] = o2;
}

// ---------------------------------------------------------------
extern "C" void kernel_launch(void* const* d_in, const int* in_sizes, int n_in,
                              void* d_out, int out_size) {
    const float* x       = (const float*)d_in[0];
    const float* w_mixer = (const float*)d_in[1];
    const float* g_mnorm = (const float*)d_in[2];
    const float* b_mnorm = (const float*)d_in[3];
    const float* w_h1    = (const float*)d_in[4];
    const float* w_v1    = (const float*)d_in[5];
    const float* w_h2    = (const float*)d_in[6];
    const float* w_v2    = (const float*)d_in[7];
    const float* g_norm  = (const float*)d_in[8];
    const float* b_norm  = (const float*)d_in[9];

    k_pool_focus<<<dim3(4, 64, 16), 256>>>(x);
    k_mixer<<<dim3(9, 9, 16), 256>>>(w_mixer);
    k_conv<<<BB*32, 256>>>(w_h1, w_v1, w_h2, w_v2, g_mnorm, b_mnorm);
    k_final<<<dim3(9, 64, 16), 192>>>(x, (float*)d_out, g_mnorm, b_mnorm, g_norm, b_norm);
}

// round 11
// speedup vs baseline: 1.2874x; 1.2077x over previous
#include <cuda_runtime.h>
#include <cuda_fp16.h>
#include <math.h>

#define BB 16
#define CC 64
#define HH 144
#define WW 144
#define hs 48
#define wsz 48
#define G9 9
#define C9 576
#define HW (hs*wsz)          // 2304
#define NPIX 36864.0f        // B*h*w
#define EPSV 1e-5f

typedef unsigned long long ull;
typedef unsigned int uint32;

// ---- packed f32x2 helpers (sm_103a FFMA2 path) ----
__device__ __forceinline__ ull ffma2(ull a, ull b, ull c) {
    ull d; asm("fma.rn.f32x2 %0, %1, %2, %3;" : "=l"(d) : "l"(a), "l"(b), "l"(c)); return d;
}
__device__ __forceinline__ ull add2(ull a, ull b) {
    ull d; asm("add.rn.f32x2 %0, %1, %2;" : "=l"(d) : "l"(a), "l"(b)); return d;
}
__device__ __forceinline__ ull pack2(float lo, float hi) {
    ull d; asm("mov.b64 %0, {%1, %2};" : "=l"(d) : "f"(lo), "f"(hi)); return d;
}
__device__ __forceinline__ void unpack2(ull v, float& lo, float& hi) {
    asm("mov.b64 {%0, %1}, %2;" : "=f"(lo), "=f"(hi) : "l"(v));
}
__device__ __forceinline__ uint32 f2tf32(float f) {
    uint32 r; asm("cvt.rna.tf32.f32 %0, %1;" : "=r"(r) : "f"(f)); return r;
}
__device__ __forceinline__ void mma_tf32(float c[4], uint32 a0, uint32 a1, uint32 a2, uint32 a3,
                                         uint32 b0, uint32 b1) {
    asm("mma.sync.aligned.m16n8k8.row.col.f32.tf32.tf32.f32 "
        "{%0,%1,%2,%3}, {%4,%5,%6,%7}, {%8,%9}, {%0,%1,%2,%3};"
        : "+f"(c[0]), "+f"(c[1]), "+f"(c[2]), "+f"(c[3])
        : "r"(a0), "r"(a1), "r"(a2), "r"(a3), "r"(b0), "r"(b1));
}

// ---- static scratch ----
__device__ __align__(16) __half g_focus[BB*C9*HW];   // 42.5 MB
__device__ __align__(16) __half g_mixed[BB*C9*HW];   // 42.5 MB
__device__ __align__(16) float  g_s[BB*CC*HW];       // 9.4 MB
__device__ float  g_sum1[C9], g_sq1[C9];
__device__ float  g_sum2[CC], g_sq2[CC];

// ---------------------------------------------------------------
// K1: maxpool3x3 + focus, smem-tiled separable max.
// ---------------------------------------------------------------
__global__ __launch_bounds__(256)
void k_pool_focus(const float* __restrict__ x) {
    __shared__ float xt[38*144];
    __shared__ float hm[38*144];
    int tid = threadIdx.x;
    int tile = blockIdx.x, c = blockIdx.y, b = blockIdx.z;
    if (tile == 0 && c == 0 && b == 0) {
        for (int i = tid; i < C9; i += 256) { g_sum1[i] = 0.f; g_sq1[i] = 0.f; }
        if (tid < CC) { g_sum2[tid] = 0.f; g_sq2[tid] = 0.f; }
    }
    int y0 = tile*36 - 1;
    const float* xp = x + (size_t)(b*CC + c) * HH * WW;
    for (int e = tid; e < 38*36; e += 256) {
        int rr = e / 36, c4 = e % 36;
        int y = y0 + rr;
        float4 v;
        if (y >= 0 && y < HH) v = *(const float4*)&xp[(size_t)y*WW + c4*4];
        else v = make_float4(-INFINITY, -INFINITY, -INFINITY, -INFINITY);
        *(float4*)&xt[rr*144 + c4*4] = v;
    }
    __syncthreads();
    for (int e = tid; e < 38*144; e += 256) {
        int xc = e % 144;
        float m = xt[e];
        if (xc > 0)   m = fmaxf(m, xt[e-1]);
        if (xc < 143) m = fmaxf(m, xt[e+1]);
        hm[e] = m;
    }
    __syncthreads();
    for (int e = tid; e < 576; e += 256) {
        int hl = e / 48, ww = e % 48;
        int base = (3*hl)*144 + 3*ww;
        float h[5][3];
#pragma unroll
        for (int dy = 0; dy < 5; dy++)
#pragma unroll
            for (int j = 0; j < 3; j++) h[dy][j] = hm[base + dy*144 + j];
        int hh = tile*12 + hl;
        size_t pbase = (size_t)b*C9*HW + (size_t)hh*wsz + ww;
#pragma unroll
        for (int i = 0; i < 3; i++)
#pragma unroll
            for (int j = 0; j < 3; j++) {
                float m = fmaxf(fmaxf(h[i][j], h[i+1][j]), h[i+2][j]);
                g_focus[pbase + (size_t)((i*3+j)*CC + c)*HW] = __float2half(m);
            }
    }
}

// ---------------------------------------------------------------
// K2: mixer GEMM on tf32 tensor cores (mma.m16n8k8).
// Block = 128 thr (4 warps), tile 64o x 64p, K=64.
// Xs[k][p] stride 72 -> conflict-free B-frag; Ws[o][k] stride 68
// -> conflict-free A-frag. fp16 in / fp16 out, fp32 accumulate.
// BN1 stats from C-fragments via quad shuffles.
// ---------------------------------------------------------------
__global__ __launch_bounds__(128)
void k_mixer(const float* __restrict__ wmix) {
    __shared__ __align__(16) uint32 Xs[64*72];   // 18.4 KB (tf32 bits)
    __shared__ __align__(16) uint32 Ws[64*68];   // 17.4 KB (tf32 bits)
    int tid = threadIdx.x;
    int pt = blockIdx.x, g = blockIdx.y, b = blockIdx.z;   // pt: 0..35 (64-px tiles)
    int lane = tid & 31, wid = tid >> 5;
    int gid = lane >> 2, tig = lane & 3;

    size_t base = ((size_t)b*C9 + g*CC) * HW + pt*64;

    // stage X: 64 k-rows x 64 px, fp16 -> tf32 bits
    {
        int k = tid >> 1, p0 = (tid & 1) * 32;
        const __half* src = g_focus + base + (size_t)k*HW + p0;
        uint32* dst = Xs + k*72 + p0;
#pragma unroll
        for (int j = 0; j < 4; j++) {
            uint4 u = *(const uint4*)(src + j*8);
            const __half2* h = (const __half2*)&u;
#pragma unroll
            for (int q = 0; q < 4; q++) {
                float2 f = __half22float2(h[q]);
                dst[j*8 + q*2]     = f2tf32(f.x);
                dst[j*8 + q*2 + 1] = f2tf32(f.y);
            }
        }
    }
    // stage W: 64 o-rows x 64 k, fp32 -> tf32 bits
    {
        const float* wg = wmix + g*4096;
        int o = tid >> 1, k0 = (tid & 1) * 32;
#pragma unroll
        for (int j = 0; j < 32; j += 4) {
            float4 w = *(const float4*)&wg[o*64 + k0 + j];
            Ws[o*68 + k0 + j]     = f2tf32(w.x);
            Ws[o*68 + k0 + j + 1] = f2tf32(w.y);
            Ws[o*68 + k0 + j + 2] = f2tf32(w.z);
            Ws[o*68 + k0 + j + 3] = f2tf32(w.w);
        }
    }
    __syncthreads();

    int o0 = wid * 16;                  // warp owns 16 output channels, all 64 px
    float acc[8][4];
#pragma unroll
    for (int nt = 0; nt < 8; nt++)
#pragma unroll
        for (int j = 0; j < 4; j++) acc[nt][j] = 0.f;

#pragma unroll
    for (int kk = 0; kk < 8; kk++) {
        int k0 = kk * 8;
        uint32 a0 = Ws[(o0 + gid)    *68 + k0 + tig];
        uint32 a1 = Ws[(o0 + gid + 8)*68 + k0 + tig];
        uint32 a2 = Ws[(o0 + gid)    *68 + k0 + tig + 4];
        uint32 a3 = Ws[(o0 + gid + 8)*68 + k0 + tig + 4];
#pragma unroll
        for (int nt = 0; nt < 8; nt++) {
            int p0 = nt * 8;
            uint32 b0 = Xs[(k0 + tig)    *72 + p0 + gid];
            uint32 b1 = Xs[(k0 + tig + 4)*72 + p0 + gid];
            mma_tf32(acc[nt], a0, a1, a2, a3, b0, b1);
        }
    }

    // store fp16 + bn1 stats
    __half* outp = g_mixed + base;
    int r0 = o0 + gid, r1 = r0 + 8;
    float s0 = 0.f, q0 = 0.f, s1 = 0.f, q1 = 0.f;
#pragma unroll
    for (int nt = 0; nt < 8; nt++) {
        int p = nt*8 + 2*tig;
        *(__half2*)&outp[(size_t)r0*HW + p] = __floats2half2_rn(acc[nt][0], acc[nt][1]);
        *(__half2*)&outp[(size_t)r1*HW + p] = __floats2half2_rn(acc[nt][2], acc[nt][3]);
        s0 += acc[nt][0] + acc[nt][1];
        q0 += acc[nt][0]*acc[nt][0] + acc[nt][1]*acc[nt][1];
        s1 += acc[nt][2] + acc[nt][3];
        q1 += acc[nt][2]*acc[nt][2] + acc[nt][3]*acc[nt][3];
    }
#pragma unroll
    for (int off = 1; off <= 2; off <<= 1) {
        s0 += __shfl_xor_sync(0xffffffffu, s0, off);
        q0 += __shfl_xor_sync(0xffffffffu, q0, off);
        s1 += __shfl_xor_sync(0xffffffffu, s1, off);
        q1 += __shfl_xor_sync(0xffffffffu, q1, off);
    }
    if (tig == 0) {
        atomicAdd(&g_sum1[g*CC + r0], s0);
        atomicAdd(&g_sq1[g*CC + r0], q0);
        atomicAdd(&g_sum1[g*CC + r1], s1);
        atomicAdd(&g_sq1[g*CC + r1], q1);
    }
}

// ---------------------------------------------------------------
// K3: fused 4-way dwconv, two channels per block packed f32x2.
// ---------------------------------------------------------------
#define TSTR 68
__global__ __launch_bounds__(256, 2)
void k_conv(const float* __restrict__ wh1, const float* __restrict__ wv1,
            const float* __restrict__ wh2, const float* __restrict__ wv2,
            const float* __restrict__ gm,  const float* __restrict__ bm) {
    __shared__ float2 T2[60*TSTR];
    __shared__ float2 sw1[33], sv1[33], sw2[33], sv2[33];
    __shared__ float rs0[8], rq0[8], rs1[8], rq1[8];
    int tid = threadIdx.x;
    int bc = blockIdx.x; int cp = bc & 31; int b = bc >> 5;
    int c0 = cp*2, c1 = c0 + 1;

    float mn0 = g_sum1[c0] / NPIX, mn1 = g_sum1[c1] / NPIX;
    float vr0 = g_sq1[c0] / NPIX - mn0*mn0, vr1 = g_sq1[c1] / NPIX - mn1*mn1;
    float sc0 = gm[c0] * rsqrtf(vr0 + EPSV), sc1 = gm[c1] * rsqrtf(vr1 + EPSV);
    float sh0 = bm[c0] - mn0*sc0,            sh1 = bm[c1] - mn1*sc1;

    const __half* p0 = g_mixed + ((size_t)b*C9 + c0) * HW;
    const __half* p1 = p0 + HW;
    for (int e = tid; e < 60*TSTR; e += 256) {
        int tr = e / TSTR, tc = e % TSTR;
        int r = tr - 6, q = tc - 9;
        float2 v = make_float2(0.f, 0.f);
        if (r >= 0 && r < hs && q >= 0 && q < wsz) {
            v.x = fmaf(__half2float(p0[r*wsz + q]), sc0, sh0);
            v.y = fmaf(__half2float(p1[r*wsz + q]), sc1, sh1);
        }
        T2[e] = v;
    }
    if (tid < 132) {
        int a = tid / 33, j = tid % 33;
        const float* src = (a == 0) ? wh1 : (a == 1) ? wv1 : (a == 2) ? wh2 : wv2;
        float2 w = make_float2(src[c0*33 + j], src[c1*33 + j]);
        if (a == 0) sw1[j] = w; else if (a == 1) sv1[j] = w;
        else if (a == 2) sw2[j] = w; else sv2[j] = w;
    }
    __syncthreads();

    int tx = tid & 15, ty = tid >> 4;
    int i0 = ty*3, j0 = tx*3;
    ull acc[3][3];
#pragma unroll
    for (int a = 0; a < 3; a++)
#pragma unroll
        for (int bq = 0; bq < 3; bq++) acc[a][bq] = 0ull;

#define T2AT(r,q) (*(const ull*)&T2[((r)+6)*TSTR + ((q)+9)])

#pragma unroll
    for (int v = 0; v < 3; v++) {
        ull wr[11];
#pragma unroll
        for (int u = 0; u < 11; u++) wr[u] = *(const ull*)&sw1[u*3 + v];
        int dc = v - 1;
#pragma unroll
        for (int ox = 0; ox < 3; ox++) {
            ull col[13];
#pragma unroll
            for (int t = 0; t < 13; t++) col[t] = T2AT(i0 + t - 5, j0 + ox + dc);
#pragma unroll
            for (int oy = 0; oy < 3; oy++)
#pragma unroll
                for (int u = 0; u < 11; u++)
                    acc[oy][ox] = ffma2(wr[u], col[oy + u], acc[oy][ox]);
        }
    }
#pragma unroll
    for (int u = 0; u < 3; u++) {
        ull wr[11];
#pragma unroll
        for (int v = 0; v < 11; v++) wr[v] = *(const ull*)&sv1[u*11 + v];
        int dr = u - 1;
#pragma unroll
        for (int oy = 0; oy < 3; oy++) {
            ull row[13];
#pragma unroll
            for (int t = 0; t < 13; t++) row[t] = T2AT(i0 + oy + dr, j0 + t - 5);
#pragma unroll
            for (int ox = 0; ox < 3; ox++)
#pragma unroll
                for (int v = 0; v < 11; v++)
                    acc[oy][ox] = ffma2(wr[v], row[ox + v], acc[oy][ox]);
        }
    }
#pragma unroll
    for (int ee = 0; ee < 3; ee++) {
        int e = ee - 1;
        ull wA[11], wB[11];
#pragma unroll
        for (int u = 0; u < 11; u++) wA[u] = *(const ull*)&sw2[u*3 + ee];
#pragma unroll
        for (int v = 0; v < 11; v++) wB[v] = *(const ull*)&sv2[ee*11 + v];
#pragma unroll
        for (int s2 = 0; s2 < 5; s2++) {
            int d = s2 + e;
            ull strip[15];
#pragma unroll
            for (int s = 0; s < 15; s++)
                strip[s] = T2AT(i0 + s - 6, j0 + d + 6 - s);
#pragma unroll
            for (int oy = 0; oy < 3; oy++) {
                int ox = s2 - oy;
                if (ox < 0 || ox > 2) continue;
#pragma unroll
                for (int u = 0; u < 11; u++)
                    acc[oy][ox] = ffma2(wA[u], strip[oy + u + 1], acc[oy][ox]);
#pragma unroll
                for (int v = 0; v < 11; v++)
                    acc[oy][ox] = ffma2(wB[v], strip[oy + e - v + 11], acc[oy][ox]);
            }
        }
    }
#undef T2AT

    float* sp0 = g_s + ((size_t)b*CC + c0) * HW;
    float* sp1 = sp0 + HW;
    ull S = 0ull, Q = 0ull;
#pragma unroll
    for (int oy = 0; oy < 3; oy++)
#pragma unroll
        for (int ox = 0; ox < 3; ox++) {
            float v0, v1; unpack2(acc[oy][ox], v0, v1);
            sp0[(i0 + oy)*wsz + j0 + ox] = v0;
            sp1[(i0 + oy)*wsz + j0 + ox] = v1;
            S = add2(S, acc[oy][ox]);
            Q = ffma2(acc[oy][ox], acc[oy][ox], Q);
        }
    float s0, s1, q0, q1; unpack2(S, s0, s1); unpack2(Q, q0, q1);
#pragma unroll
    for (int off = 16; off > 0; off >>= 1) {
        s0 += __shfl_xor_sync(0xffffffffu, s0, off);
        q0 += __shfl_xor_sync(0xffffffffu, q0, off);
        s1 += __shfl_xor_sync(0xffffffffu, s1, off);
        q1 += __shfl_xor_sync(0xffffffffu, q1, off);
    }
    int lane = tid & 31, wid = tid >> 5;
    if (lane == 0) { rs0[wid] = s0; rq0[wid] = q0; rs1[wid] = s1; rq1[wid] = q1; }
    __syncthreads();
    if (tid == 0) {
        float a0 = 0.f, b0v = 0.f, a1 = 0.f, b1v = 0.f;
#pragma unroll
        for (int w = 0; w < 8; w++) { a0 += rs0[w]; b0v += rq0[w]; a1 += rs1[w]; b1v += rq1[w]; }
        atomicAdd(&g_sum2[c0], a0); atomicAdd(&g_sq2[c0], b0v);
        atomicAdd(&g_sum2[c1], a1); atomicAdd(&g_sq2[c1], b1v);
    }
}

// ---------------------------------------------------------------
// K4: concat + pixel_shuffle3 + sigmoid gate. Barrier-free 128-bit.
// ---------------------------------------------------------------
__global__ __launch_bounds__(192)
void k_final(const float* __restrict__ x, float* __restrict__ out,
             const float* __restrict__ gm, const float* __restrict__ bm,
             const float* __restrict__ gn, const float* __restrict__ bn) {
    __shared__ float ssc[9], ssh[9];
    int c = blockIdx.y, b = blockIdx.z;
    int tid = threadIdx.x;
    if (tid < 9) {
        int k = c*9 + tid;
        float mean, var, sc, sh;
        if (k < CC) {
            mean = g_sum2[k] / NPIX; var = g_sq2[k] / NPIX - mean*mean;
            sc = gn[k] * rsqrtf(var + EPSV); sh = bn[k] - mean*sc;
        } else {
            mean = g_sum1[k] / NPIX; var = g_sq1[k] / NPIX - mean*mean;
            sc = gm[k] * rsqrtf(var + EPSV); sh = bm[k] - mean*sc;
        }
        ssc[tid] = sc; ssh[tid] = sh;
    }
    __syncthreads();

    int row = blockIdx.x * 16 + tid / 12;
    int k   = tid % 12;
    int r = row % 3, hh = row / 3, ww0 = k * 4;
    size_t spix = (size_t)hh*wsz + ww0;

    float sg[3][4];
#pragma unroll
    for (int s = 0; s < 3; s++) {
        int t = r*3 + s;
        int ch = c*9 + t;
        float4 v;
        if (ch < CC) {
            v = *(const float4*)&g_s[((size_t)b*CC + ch)*HW + spix];
        } else {
            uint2 u = *(const uint2*)&g_mixed[((size_t)b*C9 + ch)*HW + spix];
            __half2 h0 = *(__half2*)&u.x, h1 = *(__half2*)&u.y;
            v = make_float4(__low2float(h0), __high2float(h0),
                            __low2float(h1), __high2float(h1));
        }
        float sc = ssc[t], sh = ssh[t];
        sg[s][0] = 1.f / (1.f + __expf(-fmaf(v.x, sc, sh)));
        sg[s][1] = 1.f / (1.f + __expf(-fmaf(v.y, sc, sh)));
        sg[s][2] = 1.f / (1.f + __expf(-fmaf(v.z, sc, sh)));
        sg[s][3] = 1.f / (1.f + __expf(-fmaf(v.w, sc, sh)));
    }

    const float* xr = x   + ((size_t)(b*CC + c)*HH + row)*WW + k*12;
    float*       op = out + ((size_t)(b*CC + c)*HH + row)*WW + k*12;
    float4 x0 = *(const float4*)&xr[0];
    float4 x1 = *(const float4*)&xr[4];
    float4 x2 = *(const float4*)&xr[8];
    float4 o0 = make_float4(x0.x*sg[0][0], x0.y*sg[1][0], x0.z*sg[2][0], x0.w*sg[0][1]);
    float4 o1 = make_float4(x1.x*sg[1][1], x1.y*sg[2][1], x1.z*sg[0][2], x1.w*sg[1][2]);
    float4 o2 = make_float4(x2.x*sg[2][2], x2.y*sg[0][3], x2.z*sg[1][3], x2.w*sg[2][3]);
    *(float4*)&op[0] = o0;
    *(float4*)&op[4] = o1;
    *(float4*)&op[8] = o2;
}

// ---------------------------------------------------------------
extern "C" void kernel_launch(void* const* d_in, const int* in_sizes, int n_in,
                              void* d_out, int out_size) {
    const float* x       = (const float*)d_in[0];
    const float* w_mixer = (const float*)d_in[1];
    const float* g_mnorm = (const float*)d_in[2];
    const float* b_mnorm = (const float*)d_in[3];
    const float* w_h1    = (const float*)d_in[4];
    const float* w_v1    = (const float*)d_in[5];
    const float* w_h2    = (const float*)d_in[6];
    const float* w_v2    = (const float*)d_in[7];
    const float* g_norm  = (const float*)d_in[8];
    const float* b_norm  = (const float*)d_in[9];

    k_pool_focus<<<dim3(4, 64, 16), 256>>>(x);
    k_mixer<<<dim3(36, 9, 16), 128>>>(w_mixer);
    k_conv<<<BB*32, 256>>>(w_h1, w_v1, w_h2, w_v2, g_mnorm, b_mnorm);
    k_final<<<dim3(9, 64, 16), 192>>>(x, (float*)d_out, g_mnorm, b_mnorm, g_norm, b_norm);
}

// round 14
// speedup vs baseline: 1.2993x; 1.0092x over previous
#include <cuda_runtime.h>
#include <cuda_fp16.h>
#include <math.h>

#define BB 16
#define CC 64
#define HH 144
#define WW 144
#define hs 48
#define wsz 48
#define G9 9
#define C9 576
#define HW (hs*wsz)          // 2304
#define NPIX 36864.0f        // B*h*w
#define EPSV 1e-5f

typedef unsigned long long ull;
typedef unsigned int uint32;

// ---- packed f32x2 helpers (sm_103a FFMA2 path) ----
__device__ __forceinline__ ull ffma2(ull a, ull b, ull c) {
    ull d; asm("fma.rn.f32x2 %0, %1, %2, %3;" : "=l"(d) : "l"(a), "l"(b), "l"(c)); return d;
}
__device__ __forceinline__ ull add2(ull a, ull b) {
    ull d; asm("add.rn.f32x2 %0, %1, %2;" : "=l"(d) : "l"(a), "l"(b)); return d;
}
__device__ __forceinline__ void unpack2(ull v, float& lo, float& hi) {
    asm("mov.b64 {%0, %1}, %2;" : "=f"(lo), "=f"(hi) : "l"(v));
}
__device__ __forceinline__ uint32 f2tf32(float f) {
    uint32 r; asm("cvt.rna.tf32.f32 %0, %1;" : "=r"(r) : "f"(f)); return r;
}
__device__ __forceinline__ void mma_tf32(float c[4], uint32 a0, uint32 a1, uint32 a2, uint32 a3,
                                         uint32 b0, uint32 b1) {
    asm("mma.sync.aligned.m16n8k8.row.col.f32.tf32.tf32.f32 "
        "{%0,%1,%2,%3}, {%4,%5,%6,%7}, {%8,%9}, {%0,%1,%2,%3};"
        : "+f"(c[0]), "+f"(c[1]), "+f"(c[2]), "+f"(c[3])
        : "r"(a0), "r"(a1), "r"(a2), "r"(a3), "r"(b0), "r"(b1));
}

// ---- static scratch ----
__device__ __align__(16) __half g_mixed[BB*C9*HW];   // 42.5 MB
__device__ __align__(16) float  g_s[BB*CC*HW];       // 9.4 MB
__device__ float  g_sum1[C9], g_sq1[C9];
__device__ float  g_sum2[CC], g_sq2[CC];

// ---------------------------------------------------------------
// K0: zero BN accumulators (must precede k_pm which accumulates).
// ---------------------------------------------------------------
__global__ void k_zero() {
    int i = threadIdx.x;
    if (i < C9) { g_sum1[i] = 0.f; g_sq1[i] = 0.f; }
    if (i < CC) { g_sum2[i] = 0.f; g_sq2[i] = 0.f; }
}

// ---------------------------------------------------------------
// K1: FUSED maxpool3x3 + focus + mixer GEMM (tf32 tensor cores).
// Block = (focus row hh, batch b), 256 threads (8 warps).
// Dynamic smem (91136 B -> 2 blocks/SM):
//   vm[3]: 64ch x 144 fp16 vertical 3-max planes   3 x 18432 B
//   Xs:    64k x 72 tf32 pooled X tile             18432 B
//   Ws:    64o x 68 tf32 mixer weights             17408 B
// Staging builds vm planes directly (no raw x buffer).
// Per group g=(i,j): Xs from horiz 3-max of vm[i] at 3ww+j,
// then 64o x 48p x 64k MMA; warp w owns 16ch x 24px:
//   o0 = (w>>1)*16, pbase = (w&1)*24.
// ---------------------------------------------------------------
#define VM_OFF 0
#define XT_OFF 55296
#define WS_OFF 73728
#define PM_SMEM 91136

__global__ __launch_bounds__(256)
void k_pm(const float* __restrict__ x, const float* __restrict__ wmix) {
    extern __shared__ __align__(16) char dyn[];
    __half* vm = (__half*)(dyn + VM_OFF);     // 3 planes of 9216 halves
    uint32* Xs = (uint32*)(dyn + XT_OFF);
    uint32* Ws = (uint32*)(dyn + WS_OFF);

    int tid = threadIdx.x;
    int hh = blockIdx.x, b = blockIdx.y;
    int lane = tid & 31, wid = tid >> 5;
    int gid = lane >> 2, tig = lane & 3;

    // ---- stage: load 5 x rows, build 3 vertical-max planes (fp16)
    const float* xb = x + (size_t)b*CC*HH*WW;
#pragma unroll
    for (int it = 0; it < 9; it++) {
        int e = tid + it*256;                 // 2304 float4 chunks (64ch x 36)
        int c = e / 36, c4 = e % 36;
        float4 xv[5];
#pragma unroll
        for (int r = 0; r < 5; r++) {
            int y = 3*hh - 1 + r;
            if (y >= 0 && y < HH) xv[r] = *(const float4*)&xb[((size_t)c*HH + y)*WW + c4*4];
            else xv[r] = make_float4(-INFINITY,-INFINITY,-INFINITY,-INFINITY);
        }
#pragma unroll
        for (int i = 0; i < 3; i++) {
            float4 m;
            m.x = fmaxf(fmaxf(xv[i].x, xv[i+1].x), xv[i+2].x);
            m.y = fmaxf(fmaxf(xv[i].y, xv[i+1].y), xv[i+2].y);
            m.z = fmaxf(fmaxf(xv[i].z, xv[i+1].z), xv[i+2].z);
            m.w = fmaxf(fmaxf(xv[i].w, xv[i+1].w), xv[i+2].w);
            __half2 h0 = __floats2half2_rn(m.x, m.y);
            __half2 h1 = __floats2half2_rn(m.z, m.w);
            uint2 st; st.x = *(uint32*)&h0; st.y = *(uint32*)&h1;
            *(uint2*)&vm[i*9216 + c*144 + c4*4] = st;
        }
    }

#pragma unroll 1
    for (int g = 0; g < G9; g++) {
        int i = g / 3, j = g - i*3;
        __syncthreads();   // staging done (g=0) / prior MMA reads done (g>0)
        // ---- Xs[c][ww] (tf32): horizontal 3-max of vm[i] at col 3ww+j
        const __half* vmp = vm + i*9216;
#pragma unroll
        for (int it = 0; it < 12; it++) {
            int e = tid + it*256;             // 64*48
            int c = e / 48, ww = e % 48;
            int col = 3*ww + j;
            __half m = vmp[c*144 + col];
            if (col > 0)   m = __hmax(m, vmp[c*144 + col - 1]);
            if (col < 143) m = __hmax(m, vmp[c*144 + col + 1]);
            Xs[c*72 + ww] = f2tf32(__half2float(m));
        }
        // ---- Ws for group g (fp32 -> tf32)
        {
            const float* wg = wmix + g*4096;
#pragma unroll
            for (int it = 0; it < 4; it++) {
                int e = tid + it*256;         // 1024 float4
                int o = e >> 4, k4 = (e & 15) * 4;
                float4 w = *(const float4*)&wg[o*64 + k4];
                Ws[o*68 + k4]     = f2tf32(w.x);
                Ws[o*68 + k4 + 1] = f2tf32(w.y);
                Ws[o*68 + k4 + 2] = f2tf32(w.z);
                Ws[o*68 + k4 + 3] = f2tf32(w.w);
            }
        }
        __syncthreads();  // Xs/Ws ready
        // ---- MMA: warp owns 16 channels x 24 px
        int o0 = (wid >> 1) * 16;
        int pbase = (wid & 1) * 24;
        float acc[3][4];
#pragma unroll
        for (int nt = 0; nt < 3; nt++)
#pragma unroll
            for (int q = 0; q < 4; q++) acc[nt][q] = 0.f;
#pragma unroll
        for (int kk = 0; kk < 8; kk++) {
            int k0 = kk * 8;
            uint32 a0 = Ws[(o0 + gid)    *68 + k0 + tig];
            uint32 a1 = Ws[(o0 + gid + 8)*68 + k0 + tig];
            uint32 a2 = Ws[(o0 + gid)    *68 + k0 + tig + 4];
            uint32 a3 = Ws[(o0 + gid + 8)*68 + k0 + tig + 4];
#pragma unroll
            for (int nt = 0; nt < 3; nt++) {
                int p0 = pbase + nt * 8;
                uint32 b0 = Xs[(k0 + tig)    *72 + p0 + gid];
                uint32 b1 = Xs[(k0 + tig + 4)*72 + p0 + gid];
                mma_tf32(acc[nt], a0, a1, a2, a3, b0, b1);
            }
        }
        // ---- store fp16 + bn1 stats
        __half* outp = g_mixed + ((size_t)b*C9 + g*CC)*HW + hh*wsz;
        int r0 = o0 + gid, r1 = r0 + 8;
        float s0 = 0.f, q0 = 0.f, s1 = 0.f, q1 = 0.f;
#pragma unroll
        for (int nt = 0; nt < 3; nt++) {
            int p = pbase + nt*8 + 2*tig;
            *(__half2*)&outp[(size_t)r0*HW + p] = __floats2half2_rn(acc[nt][0], acc[nt][1]);
            *(__half2*)&outp[(size_t)r1*HW + p] = __floats2half2_rn(acc[nt][2], acc[nt][3]);
            s0 += acc[nt][0] + acc[nt][1];
            q0 += acc[nt][0]*acc[nt][0] + acc[nt][1]*acc[nt][1];
            s1 += acc[nt][2] + acc[nt][3];
            q1 += acc[nt][2]*acc[nt][2] + acc[nt][3]*acc[nt][3];
        }
#pragma unroll
        for (int off = 1; off <= 2; off <<= 1) {
            s0 += __shfl_xor_sync(0xffffffffu, s0, off);
            q0 += __shfl_xor_sync(0xffffffffu, q0, off);
            s1 += __shfl_xor_sync(0xffffffffu, s1, off);
            q1 += __shfl_xor_sync(0xffffffffu, q1, off);
        }
        if (tig == 0) {
            atomicAdd(&g_sum1[g*CC + r0], s0);
            atomicAdd(&g_sq1[g*CC + r0], q0);
            atomicAdd(&g_sum1[g*CC + r1], s1);
            atomicAdd(&g_sq1[g*CC + r1], q1);
        }
    }
}

// ---------------------------------------------------------------
// K3: fused 4-way dwconv, two channels per block packed f32x2.
// ---------------------------------------------------------------
#define TSTR 68
__global__ __launch_bounds__(256, 2)
void k_conv(const float* __restrict__ wh1, const float* __restrict__ wv1,
            const float* __restrict__ wh2, const float* __restrict__ wv2,
            const float* __restrict__ gm,  const float* __restrict__ bm) {
    __shared__ float2 T2[60*TSTR];
    __shared__ float2 sw1[33], sv1[33], sw2[33], sv2[33];
    __shared__ float rs0[8], rq0[8], rs1[8], rq1[8];
    int tid = threadIdx.x;
    int bc = blockIdx.x; int cp = bc & 31; int b = bc >> 5;
    int c0 = cp*2, c1 = c0 + 1;

    float mn0 = g_sum1[c0] / NPIX, mn1 = g_sum1[c1] / NPIX;
    float vr0 = g_sq1[c0] / NPIX - mn0*mn0, vr1 = g_sq1[c1] / NPIX - mn1*mn1;
    float sc0 = gm[c0] * rsqrtf(vr0 + EPSV), sc1 = gm[c1] * rsqrtf(vr1 + EPSV);
    float sh0 = bm[c0] - mn0*sc0,            sh1 = bm[c1] - mn1*sc1;

    const __half* p0 = g_mixed + ((size_t)b*C9 + c0) * HW;
    const __half* p1 = p0 + HW;
    for (int e = tid; e < 60*TSTR; e += 256) {
        int tr = e / TSTR, tc = e % TSTR;
        int r = tr - 6, q = tc - 9;
        float2 v = make_float2(0.f, 0.f);
        if (r >= 0 && r < hs && q >= 0 && q < wsz) {
            v.x = fmaf(__half2float(p0[r*wsz + q]), sc0, sh0);
            v.y = fmaf(__half2float(p1[r*wsz + q]), sc1, sh1);
        }
        T2[e] = v;
    }
    if (tid < 132) {
        int a = tid / 33, j = tid % 33;
        const float* src = (a == 0) ? wh1 : (a == 1) ? wv1 : (a == 2) ? wh2 : wv2;
        float2 w = make_float2(src[c0*33 + j], src[c1*33 + j]);
        if (a == 0) sw1[j] = w; else if (a == 1) sv1[j] = w;
        else if (a == 2) sw2[j] = w; else sv2[j] = w;
    }
    __syncthreads();

    int tx = tid & 15, ty = tid >> 4;
    int i0 = ty*3, j0 = tx*3;
    ull acc[3][3];
#pragma unroll
    for (int a = 0; a < 3; a++)
#pragma unroll
        for (int bq = 0; bq < 3; bq++) acc[a][bq] = 0ull;

#define T2AT(r,q) (*(const ull*)&T2[((r)+6)*TSTR + ((q)+9)])

#pragma unroll
    for (int v = 0; v < 3; v++) {
        ull wr[11];
#pragma unroll
        for (int u = 0; u < 11; u++) wr[u] = *(const ull*)&sw1[u*3 + v];
        int dc = v - 1;
#pragma unroll
        for (int ox = 0; ox < 3; ox++) {
            ull col[13];
#pragma unroll
            for (int t = 0; t < 13; t++) col[t] = T2AT(i0 + t - 5, j0 + ox + dc);
#pragma unroll
            for (int oy = 0; oy < 3; oy++)
#pragma unroll
                for (int u = 0; u < 11; u++)
                    acc[oy][ox] = ffma2(wr[u], col[oy + u], acc[oy][ox]);
        }
    }
#pragma unroll
    for (int u = 0; u < 3; u++) {
        ull wr[11];
#pragma unroll
        for (int v = 0; v < 11; v++) wr[v] = *(const ull*)&sv1[u*11 + v];
        int dr = u - 1;
#pragma unroll
        for (int oy = 0; oy < 3; oy++) {
            ull row[13];
#pragma unroll
            for (int t = 0; t < 13; t++) row[t] = T2AT(i0 + oy + dr, j0 + t - 5);
#pragma unroll
            for (int ox = 0; ox < 3; ox++)
#pragma unroll
                for (int v = 0; v < 11; v++)
                    acc[oy][ox] = ffma2(wr[v], row[ox + v], acc[oy][ox]);
        }
    }
#pragma unroll
    for (int ee = 0; ee < 3; ee++) {
        int e = ee - 1;
        ull wA[11], wB[11];
#pragma unroll
        for (int u = 0; u < 11; u++) wA[u] = *(const ull*)&sw2[u*3 + ee];
#pragma unroll
        for (int v = 0; v < 11; v++) wB[v] = *(const ull*)&sv2[ee*11 + v];
#pragma unroll
        for (int s2 = 0; s2 < 5; s2++) {
            int d = s2 + e;
            ull strip[15];
#pragma unroll
            for (int s = 0; s < 15; s++)
                strip[s] = T2AT(i0 + s - 6, j0 + d + 6 - s);
#pragma unroll
            for (int oy = 0; oy < 3; oy++) {
                int ox = s2 - oy;
                if (ox < 0 || ox > 2) continue;
#pragma unroll
                for (int u = 0; u < 11; u++)
                    acc[oy][ox] = ffma2(wA[u], strip[oy + u + 1], acc[oy][ox]);
#pragma unroll
                for (int v = 0; v < 11; v++)
                    acc[oy][ox] = ffma2(wB[v], strip[oy + e - v + 11], acc[oy][ox]);
            }
        }
    }
#undef T2AT

    float* sp0 = g_s + ((size_t)b*CC + c0) * HW;
    float* sp1 = sp0 + HW;
    ull S = 0ull, Q = 0ull;
#pragma unroll
    for (int oy = 0; oy < 3; oy++)
#pragma unroll
        for (int ox = 0; ox < 3; ox++) {
            float v0, v1; unpack2(acc[oy][ox], v0, v1);
            sp0[(i0 + oy)*wsz + j0 + ox] = v0;
            sp1[(i0 + oy)*wsz + j0 + ox] = v1;
            S = add2(S, acc[oy][ox]);
            Q = ffma2(acc[oy][ox], acc[oy][ox], Q);
        }
    float s0, s1, q0, q1; unpack2(S, s0, s1); unpack2(Q, q0, q1);
#pragma unroll
    for (int off = 16; off > 0; off >>= 1) {
        s0 += __shfl_xor_sync(0xffffffffu, s0, off);
        q0 += __shfl_xor_sync(0xffffffffu, q0, off);
        s1 += __shfl_xor_sync(0xffffffffu, s1, off);
        q1 += __shfl_xor_sync(0xffffffffu, q1, off);
    }
    int lane = tid & 31, wid = tid >> 5;
    if (lane == 0) { rs0[wid] = s0; rq0[wid] = q0; rs1[wid] = s1; rq1[wid] = q1; }
    __syncthreads();
    if (tid == 0) {
        float a0 = 0.f, b0v = 0.f, a1 = 0.f, b1v = 0.f;
#pragma unroll
        for (int w = 0; w < 8; w++) { a0 += rs0[w]; b0v += rq0[w]; a1 += rs1[w]; b1v += rq1[w]; }
        atomicAdd(&g_sum2[c0], a0); atomicAdd(&g_sq2[c0], b0v);
        atomicAdd(&g_sum2[c1], a1); atomicAdd(&g_sq2[c1], b1v);
    }
}

// ---------------------------------------------------------------
// K4: concat + pixel_shuffle3 + sigmoid gate. Barrier-free 128-bit.
// ---------------------------------------------------------------
__global__ __launch_bounds__(192)
void k_final(const float* __restrict__ x, float* __restrict__ out,
             const float* __restrict__ gm, const float* __restrict__ bm,
             const float* __restrict__ gn, const float* __restrict__ bn) {
    __shared__ float ssc[9], ssh[9];
    int c = blockIdx.y, b = blockIdx.z;
    int tid = threadIdx.x;
    if (tid < 9) {
        int k = c*9 + tid;
        float mean, var, sc, sh;
        if (k < CC) {
            mean = g_sum2[k] / NPIX; var = g_sq2[k] / NPIX - mean*mean;
            sc = gn[k] * rsqrtf(var + EPSV); sh = bn[k] - mean*sc;
        } else {
            mean = g_sum1[k] / NPIX; var = g_sq1[k] / NPIX - mean*mean;
            sc = gm[k] * rsqrtf(var + EPSV); sh = bm[k] - mean*sc;
        }
        ssc[tid] = sc; ssh[tid] = sh;
    }
    __syncthreads();

    int row = blockIdx.x * 16 + tid / 12;
    int k   = tid % 12;
    int r = row % 3, hh = row / 3, ww0 = k * 4;
    size_t spix = (size_t)hh*wsz + ww0;

    float sg[3][4];
#pragma unroll
    for (int s = 0; s < 3; s++) {
        int t = r*3 + s;
        int ch = c*9 + t;
        float4 v;
        if (ch < CC) {
            v = *(const float4*)&g_s[((size_t)b*CC + ch)*HW + spix];
        } else {
            uint2 u = *(const uint2*)&g_mixed[((size_t)b*C9 + ch)*HW + spix];
            __half2 h0 = *(__half2*)&u.x, h1 = *(__half2*)&u.y;
            v = make_float4(__low2float(h0), __high2float(h0),
                            __low2float(h1), __high2float(h1));
        }
        float sc = ssc[t], sh = ssh[t];
        sg[s][0] = 1.f / (1.f + __expf(-fmaf(v.x, sc, sh)));
        sg[s][1] = 1.f / (1.f + __expf(-fmaf(v.y, sc, sh)));
        sg[s][2] = 1.f / (1.f + __expf(-fmaf(v.z, sc, sh)));
        sg[s][3] = 1.f / (1.f + __expf(-fmaf(v.w, sc, sh)));
    }

    const float* xr = x   + ((size_t)(b*CC + c)*HH + row)*WW + k*12;
    float*       op = out + ((size_t)(b*CC + c)*HH + row)*WW + k*12;
    float4 x0 = *(const float4*)&xr[0];
    float4 x1 = *(const float4*)&xr[4];
    float4 x2 = *(const float4*)&xr[8];
    float4 o0 = make_float4(x0.x*sg[0][0], x0.y*sg[1][0], x0.z*sg[2][0], x0.w*sg[0][1]);
    float4 o1 = make_float4(x1.x*sg[1][1], x1.y*sg[2][1], x1.z*sg[0][2], x1.w*sg[1][2]);
    float4 o2 = make_float4(x2.x*sg[2][2], x2.y*sg[0][3], x2.z*sg[1][3], x2.w*sg[2][3]);
    *(float4*)&op[0] = o0;
    *(float4*)&op[4] = o1;
    *(float4*)&op[8] = o2;
}

// ---------------------------------------------------------------
extern "C" void kernel_launch(void* const* d_in, const int* in_sizes, int n_in,
                              void* d_out, int out_size) {
    const float* x       = (const float*)d_in[0];
    const float* w_mixer = (const float*)d_in[1];
    const float* g_mnorm = (const float*)d_in[2];
    const float* b_mnorm = (const float*)d_in[3];
    const float* w_h1    = (const float*)d_in[4];
    const float* w_v1    = (const float*)d_in[5];
    const float* w_h2    = (const float*)d_in[6];
    const float* w_v2    = (const float*)d_in[7];
    const float* g_norm  = (const float*)d_in[8];
    const float* b_norm  = (const float*)d_in[9];

    cudaFuncSetAttribute(k_pm, cudaFuncAttributeMaxDynamicSharedMemorySize, PM_SMEM);

    k_zero<<<1, 576>>>();
    k_pm<<<dim3(48, 16), 256, PM_SMEM>>>(x, w_mixer);
    k_conv<<<BB*32, 256>>>(w_h1, w_v1, w_h2, w_v2, g_mnorm, b_mnorm);
    k_final<<<dim3(9, 64, 16), 192>>>(x, (float*)d_out, g_mnorm, b_mnorm, g_norm, b_norm);
}